// round 14
// baseline (speedup 1.0000x reference)
#include <cuda_runtime.h>
#include <cuda_bf16.h>
#include <math.h>
#include <stdint.h>

#define BATCH 16384
#define DIM   768
#define NEXP  124
#define NCLS  6
#define NEC   (NEXP * NCLS)   // 744
#define NECP  768             // padded N for cls fc2
#define NEXPP 128             // padded N for we/ew fc2

// ---------------------------------------------------------------------------
// Scratch (static device globals; allocation-free at runtime)
// ---------------------------------------------------------------------------
__device__ __nv_bfloat16 g_xh[BATCH * DIM];
__device__ __nv_bfloat16 g_xl[BATCH * DIM];
__device__ __nv_bfloat16 g_hh[3][BATCH * DIM];
__device__ __nv_bfloat16 g_hl[3][BATCH * DIM];
__device__ __nv_bfloat16 g_w1h[3][DIM * DIM];
__device__ __nv_bfloat16 g_w1l[3][DIM * DIM];
__device__ __nv_bfloat16 g_w2ch[NECP * DIM];
__device__ __nv_bfloat16 g_w2cl[NECP * DIM];
__device__ __nv_bfloat16 g_w2eh[2][NEXPP * DIM];
__device__ __nv_bfloat16 g_w2el[2][NEXPP * DIM];
__device__ float g_cls_logits[BATCH * NEC];
__device__ float g_we_logits[BATCH * NEXP];
__device__ float g_ew_logits[BATCH * NEXP];

// ---------------------------------------------------------------------------
// Portable (sm_80+) PTX helpers
// ---------------------------------------------------------------------------
__device__ __forceinline__ uint32_t smem_u32(const void* p) {
    uint32_t a;
    asm("{ .reg .u64 t; cvta.to.shared.u64 t, %1; cvt.u32.u64 %0, t; }"
        : "=r"(a) : "l"(p));
    return a;
}

__device__ __forceinline__ void cp_async16(uint32_t dst, const void* src) {
    asm volatile("cp.async.cg.shared.global [%0], [%1], 16;"
                 :: "r"(dst), "l"(src) : "memory");
}

// mbarrier primitives (sm_80/90 features; legal on plain sm_103 target)
__device__ __forceinline__ void mbar_init(uint32_t addr, uint32_t cnt) {
    asm volatile("mbarrier.init.shared.b64 [%0], %1;"
                 :: "r"(addr), "r"(cnt) : "memory");
}
__device__ __forceinline__ void mbar_arrive(uint32_t addr) {
    asm volatile("mbarrier.arrive.shared.b64 _, [%0];"
                 :: "r"(addr) : "memory");
}
// .noinc: this thread arrives ONCE on mbar when all its prior cp.asyncs
// complete, WITHOUT bumping the expected count (fixed-count barrier).
__device__ __forceinline__ void cp_async_mbar_arrive(uint32_t addr) {
    asm volatile("cp.async.mbarrier.arrive.noinc.shared.b64 [%0];"
                 :: "r"(addr) : "memory");
}
__device__ __forceinline__ void mbar_wait(uint32_t addr, uint32_t parity) {
    uint32_t done;
    asm volatile(
        "{\n\t.reg .pred p;\n\t"
        "mbarrier.try_wait.parity.shared.b64 p, [%1], %2;\n\t"
        "selp.b32 %0, 1, 0, p;\n\t}"
        : "=r"(done) : "r"(addr), "r"(parity) : "memory");
    while (!done) {
        asm volatile(
            "{\n\t.reg .pred p;\n\t"
            "mbarrier.try_wait.parity.shared.b64 p, [%1], %2;\n\t"
            "selp.b32 %0, 1, 0, p;\n\t}"
            : "=r"(done) : "r"(addr), "r"(parity) : "memory");
    }
}

__device__ __forceinline__ void ldsm4(uint32_t* r, uint32_t addr) {
    asm volatile("ldmatrix.sync.aligned.m8n8.x4.shared.b16 {%0,%1,%2,%3}, [%4];"
                 : "=r"(r[0]), "=r"(r[1]), "=r"(r[2]), "=r"(r[3]) : "r"(addr));
}

// non-volatile: pure register semantics, lets ptxas schedule HMMA freely
__device__ __forceinline__ void mma_bf16(float* c, const uint32_t* a,
                                         uint32_t b0, uint32_t b1) {
    asm("mma.sync.aligned.m16n8k16.row.col.f32.bf16.bf16.f32 "
        "{%0,%1,%2,%3}, {%4,%5,%6,%7}, {%8,%9}, {%0,%1,%2,%3};"
        : "+f"(c[0]), "+f"(c[1]), "+f"(c[2]), "+f"(c[3])
        : "r"(a[0]), "r"(a[1]), "r"(a[2]), "r"(a[3]), "r"(b0), "r"(b1));
}

__device__ __forceinline__ float gelu_exact(float x) {
    return 0.5f * x * (1.0f + erff(x * 0.70710678118654752f));
}

// ---------------------------------------------------------------------------
// Conversions
// ---------------------------------------------------------------------------
__global__ __launch_bounds__(256)
void convert_x_k(const float* __restrict__ x,
                 __nv_bfloat16* __restrict__ xh, __nv_bfloat16* __restrict__ xl) {
    int i = blockIdx.x * blockDim.x + threadIdx.x;   // float4 index
    float4 v = ((const float4*)x)[i];
    __nv_bfloat162 h01, h23, l01, l23;
    h01.x = __float2bfloat16(v.x);
    h01.y = __float2bfloat16(v.y);
    h23.x = __float2bfloat16(v.z);
    h23.y = __float2bfloat16(v.w);
    l01.x = __float2bfloat16(v.x - __bfloat162float(h01.x));
    l01.y = __float2bfloat16(v.y - __bfloat162float(h01.y));
    l23.x = __float2bfloat16(v.z - __bfloat162float(h23.x));
    l23.y = __float2bfloat16(v.w - __bfloat162float(h23.y));
    uint2 ho, lo;
    ho.x = *(uint32_t*)&h01; ho.y = *(uint32_t*)&h23;
    lo.x = *(uint32_t*)&l01; lo.y = *(uint32_t*)&l23;
    *(uint2*)(xh + 4 * (size_t)i) = ho;
    *(uint2*)(xl + 4 * (size_t)i) = lo;
}

// Merged weight conversion: z selects which weight matrix.
__global__ __launch_bounds__(256)
void wconv_all_k(const float* __restrict__ cls_w1, const float* __restrict__ we_w1,
                 const float* __restrict__ ew_w1,  const float* __restrict__ cls_w2,
                 const float* __restrict__ we_w2,  const float* __restrict__ ew_w2)
{
    const int z = blockIdx.z;
    const float* W; int Nsrc, Npad;
    __nv_bfloat16 *Th, *Tl;
    switch (z) {
    case 0: W = cls_w1; Nsrc = DIM;  Npad = DIM;   Th = g_w1h[0]; Tl = g_w1l[0]; break;
    case 1: W = we_w1;  Nsrc = DIM;  Npad = DIM;   Th = g_w1h[1]; Tl = g_w1l[1]; break;
    case 2: W = ew_w1;  Nsrc = DIM;  Npad = DIM;   Th = g_w1h[2]; Tl = g_w1l[2]; break;
    case 3: W = cls_w2; Nsrc = NEC;  Npad = NECP;  Th = g_w2ch;   Tl = g_w2cl;   break;
    case 4: W = we_w2;  Nsrc = NEXP; Npad = NEXPP; Th = g_w2eh[0]; Tl = g_w2el[0]; break;
    default:W = ew_w2;  Nsrc = NEXP; Npad = NEXPP; Th = g_w2eh[1]; Tl = g_w2el[1]; break;
    }
    int n0 = blockIdx.x * 32, k0 = blockIdx.y * 32;
    if (n0 >= Npad) return;
    __shared__ float tile[32][33];
    int tx = threadIdx.x, ty = threadIdx.y;
    for (int i = ty; i < 32; i += 8) {
        int n = n0 + tx;
        tile[i][tx] = (n < Nsrc) ? W[(size_t)(k0 + i) * Nsrc + n] : 0.0f;
    }
    __syncthreads();
    for (int i = ty; i < 32; i += 8) {
        float v = tile[tx][i];
        __nv_bfloat16 h = __float2bfloat16(v);
        size_t o = (size_t)(n0 + i) * DIM + (k0 + tx);
        Th[o] = h;
        Tl[o] = __float2bfloat16(v - __bfloat162float(h));
    }
}

// ---------------------------------------------------------------------------
// Split-bf16 GEMM core (HMMA), 512 threads, 16 warps (4m x 4n), warp tile
// 32x32, CTA tile 128x128, BK=64, 3-buffer mbarrier pipeline (no CTA-wide
// rendezvous: cp.async.mbarrier.arrive.noinc full[b] / consumer arrive free[b]).
// ---------------------------------------------------------------------------
#define BK 64
#define NKSTAGE (DIM / BK)           // 12
#define TILE_B 16384                 // one 128x64 bf16 tile
#define STAGE_B (4 * TILE_B)         // Ah, Al, Bh, Bl  (64 KB)
#define NPIPE 3
#define SMEM_MBAR (NPIPE * STAGE_B)             // 196608
#define SMEM_TOTAL (SMEM_MBAR + 64)             // 196672

struct GemmOut {
    float* outF;               // mode 0
    __nv_bfloat16* outH;       // mode 1
    __nv_bfloat16* outL;       // mode 1
    const float* bias;
    int Nreal;
    int mode;
};

__device__ __forceinline__
void gemm_core(const __nv_bfloat16* __restrict__ Ah,
               const __nv_bfloat16* __restrict__ Al,
               const __nv_bfloat16* __restrict__ Bh,
               const __nv_bfloat16* __restrict__ Bl,
               const GemmOut& o, int m0, int n0, char* dyn)
{
    const int tid  = threadIdx.x;
    const int lane = tid & 31;
    const int wid  = tid >> 5;
    const uint32_t smem = smem_u32(dyn);
    const uint32_t mb   = smem + SMEM_MBAR;
    // full[b] = mb + 8b ; free[b] = mb + 24 + 8b

    if (tid == 0) {
#pragma unroll
        for (int b = 0; b < 3; ++b) {
            mbar_init(mb + 8 * b, 512);        // full[b]
            mbar_init(mb + 24 + 8 * b, 512);   // free[b]
        }
    }
    __syncthreads();

    const int wm = (wid >> 2) * 32;      // 0,32,64,96
    const int wn = (wid & 3) * 32;       // 0,32,64,96

    const int lr = lane & 7;
    const int aRowBase = wm + lr + 8 * ((lane >> 3) & 1);   // + 16*i
    const int aChunkSel = lane >> 4;
    const int bRowBase = wn + lr + 8 * (lane >> 4);         // + 16*jj
    const int bChunkSel = (lane >> 3) & 1;

    float acc[2][4][4];
#pragma unroll
    for (int i = 0; i < 2; i++)
#pragma unroll
        for (int j = 0; j < 4; j++)
#pragma unroll
            for (int r = 0; r < 4; r++) acc[i][j][r] = 0.0f;

    auto load_stage = [&](int s) {
        const int k0 = s * BK;
        const uint32_t sb = smem + (s % NPIPE) * STAGE_B;
#pragma unroll
        for (int it = 0; it < 2; ++it) {
            int idx = it * 512 + tid;     // 0..1023
            int row = idx >> 3;           // 0..127
            int ch  = idx & 7;            // 16B chunk
            uint32_t sw = (uint32_t)(row * 128 + ((ch ^ (row & 7)) << 4));
            size_t aoff = (size_t)(m0 + row) * DIM + k0 + ch * 8;
            size_t boff = (size_t)(n0 + row) * DIM + k0 + ch * 8;
            cp_async16(sb + 0 * TILE_B + sw, Ah + aoff);
            cp_async16(sb + 1 * TILE_B + sw, Al + aoff);
            cp_async16(sb + 2 * TILE_B + sw, Bh + boff);
            cp_async16(sb + 3 * TILE_B + sw, Bl + boff);
        }
    };

    load_stage(0); cp_async_mbar_arrive(mb + 0);       // full[0]
    load_stage(1); cp_async_mbar_arrive(mb + 8);       // full[1]

#pragma unroll 1
    for (int s = 0; s < NKSTAGE; ++s) {
        const int b = s % 3;
        mbar_wait(mb + 8 * b, (uint32_t)((s / 3) & 1));   // full[b]
        const uint32_t base = smem + b * STAGE_B;

#pragma unroll
        for (int kk = 0; kk < 4; ++kk) {
            // mid-compute prefetch: stage s+2 into buffer (s+2)%3
            if (kk == 2 && s + 2 < NKSTAGE) {
                const int nb = (s + 2) % 3;
                if (s >= 1)
                    mbar_wait(mb + 24 + 8 * nb, (uint32_t)(((s - 1) / 3) & 1)); // free[nb]
                load_stage(s + 2);
                cp_async_mbar_arrive(mb + 8 * nb);        // full[nb]
            }

            uint32_t ah[2][4], al[2][4], bh[2][4], bl[2][4];
#pragma unroll
            for (int i = 0; i < 2; ++i) {
                int r = aRowBase + 16 * i;
                uint32_t addr = base + (uint32_t)(r * 128)
                              + (uint32_t)((((2 * kk + aChunkSel) ^ (r & 7)) << 4));
                ldsm4(ah[i], addr);
            }
#pragma unroll
            for (int jj = 0; jj < 2; ++jj) {
                int r = bRowBase + 16 * jj;
                uint32_t addr = base + 2 * TILE_B + (uint32_t)(r * 128)
                              + (uint32_t)((((2 * kk + bChunkSel) ^ (r & 7)) << 4));
                ldsm4(bh[jj], addr);
            }
            // hi x hi MMAs while lo fragments load
#pragma unroll
            for (int i = 0; i < 2; ++i)
#pragma unroll
                for (int j = 0; j < 4; ++j)
                    mma_bf16(acc[i][j], ah[i],
                             bh[j >> 1][(j & 1) * 2], bh[j >> 1][(j & 1) * 2 + 1]);
#pragma unroll
            for (int i = 0; i < 2; ++i) {
                int r = aRowBase + 16 * i;
                uint32_t addr = base + TILE_B + (uint32_t)(r * 128)
                              + (uint32_t)((((2 * kk + aChunkSel) ^ (r & 7)) << 4));
                ldsm4(al[i], addr);
            }
#pragma unroll
            for (int jj = 0; jj < 2; ++jj) {
                int r = bRowBase + 16 * jj;
                uint32_t addr = base + 3 * TILE_B + (uint32_t)(r * 128)
                              + (uint32_t)((((2 * kk + bChunkSel) ^ (r & 7)) << 4));
                ldsm4(bl[jj], addr);
            }
            if (kk == 3)
                mbar_arrive(mb + 24 + 8 * b);             // free[b]: done reading
#pragma unroll
            for (int i = 0; i < 2; ++i)
#pragma unroll
                for (int j = 0; j < 4; ++j)
                    mma_bf16(acc[i][j], ah[i],
                             bl[j >> 1][(j & 1) * 2], bl[j >> 1][(j & 1) * 2 + 1]);
#pragma unroll
            for (int i = 0; i < 2; ++i)
#pragma unroll
                for (int j = 0; j < 4; ++j)
                    mma_bf16(acc[i][j], al[i],
                             bh[j >> 1][(j & 1) * 2], bh[j >> 1][(j & 1) * 2 + 1]);
        }
    }

    // ---- epilogue from registers ----
    const int qrow = lane >> 2;
    const int qcol = (lane & 3) * 2;
#pragma unroll
    for (int i = 0; i < 2; ++i) {
        int r0 = m0 + wm + 16 * i + qrow;
        int r1 = r0 + 8;
#pragma unroll
        for (int j = 0; j < 4; ++j) {
            int col = n0 + wn + j * 8 + qcol;
            if (o.mode == 1) {
                float2 bv = *(const float2*)(o.bias + col);
                float g0 = gelu_exact(acc[i][j][0] + bv.x);
                float g1 = gelu_exact(acc[i][j][1] + bv.y);
                float g2 = gelu_exact(acc[i][j][2] + bv.x);
                float g3 = gelu_exact(acc[i][j][3] + bv.y);
                __nv_bfloat162 h01, h23, l01, l23;
                h01.x = __float2bfloat16(g0); h01.y = __float2bfloat16(g1);
                h23.x = __float2bfloat16(g2); h23.y = __float2bfloat16(g3);
                l01.x = __float2bfloat16(g0 - __bfloat162float(h01.x));
                l01.y = __float2bfloat16(g1 - __bfloat162float(h01.y));
                l23.x = __float2bfloat16(g2 - __bfloat162float(h23.x));
                l23.y = __float2bfloat16(g3 - __bfloat162float(h23.y));
                *(__nv_bfloat162*)(o.outH + (size_t)r0 * DIM + col) = h01;
                *(__nv_bfloat162*)(o.outH + (size_t)r1 * DIM + col) = h23;
                *(__nv_bfloat162*)(o.outL + (size_t)r0 * DIM + col) = l01;
                *(__nv_bfloat162*)(o.outL + (size_t)r1 * DIM + col) = l23;
            } else {
                if (col < o.Nreal) {
                    float2 bv = *(const float2*)(o.bias + col);
                    float2 o0, o1;
                    o0.x = acc[i][j][0] + bv.x; o0.y = acc[i][j][1] + bv.y;
                    o1.x = acc[i][j][2] + bv.x; o1.y = acc[i][j][3] + bv.y;
                    *(float2*)(o.outF + (size_t)r0 * o.Nreal + col) = o0;
                    *(float2*)(o.outF + (size_t)r1 * o.Nreal + col) = o1;
                }
            }
        }
    }
}

// ---- merged fc1: grid (18, 128); layer = bx/6, n0 = (bx%6)*128 ----
__global__ __launch_bounds__(512, 1)
void fc1_merged(const float* __restrict__ b_cls, const float* __restrict__ b_we,
                const float* __restrict__ b_ew)
{
    extern __shared__ __align__(1024) char dyn[];
    const int bx = blockIdx.x;
    const int layer = bx / 6;
    const int n0 = (bx % 6) * 128;
    const int m0 = blockIdx.y * 128;
    GemmOut o;
    o.outF = nullptr;
    o.outH = g_hh[layer];
    o.outL = g_hl[layer];
    o.bias = (layer == 0) ? b_cls : (layer == 1) ? b_we : b_ew;
    o.Nreal = DIM;
    o.mode = 1;
    gemm_core(g_xh, g_xl, g_w1h[layer], g_w1l[layer], o, m0, n0, dyn);
}

// ---- merged fc2: grid (8, 128) ----
__global__ __launch_bounds__(512, 1)
void fc2_merged(const float* __restrict__ b_cls, const float* __restrict__ b_we,
                const float* __restrict__ b_ew)
{
    extern __shared__ __align__(1024) char dyn[];
    const int bx = blockIdx.x;
    const int m0 = blockIdx.y * 128;
    GemmOut o;
    o.outH = nullptr; o.outL = nullptr; o.mode = 0;
    const __nv_bfloat16 *Ah, *Al, *Bh, *Bl;
    int n0;
    if (bx < 6) {
        Ah = g_hh[0]; Al = g_hl[0]; Bh = g_w2ch; Bl = g_w2cl;
        o.outF = g_cls_logits; o.bias = b_cls; o.Nreal = NEC; n0 = bx * 128;
    } else if (bx == 6) {
        Ah = g_hh[1]; Al = g_hl[1]; Bh = g_w2eh[0]; Bl = g_w2el[0];
        o.outF = g_we_logits; o.bias = b_we; o.Nreal = NEXP; n0 = 0;
    } else {
        Ah = g_hh[2]; Al = g_hl[2]; Bh = g_w2eh[1]; Bl = g_w2el[1];
        o.outF = g_ew_logits; o.bias = b_ew; o.Nreal = NEXP; n0 = 0;
    }
    gemm_core(Ah, Al, Bh, Bl, o, m0, n0, dyn);
}

// ---------------------------------------------------------------------------
// Row-wise epilogue (unchanged, verified)
// ---------------------------------------------------------------------------
__global__ __launch_bounds__(128)
void epilogue_kernel(const float* __restrict__ we_l,
                     const float* __restrict__ ew_l,
                     const float* __restrict__ cls_l,
                     const int*   __restrict__ n_experts,
                     float* __restrict__ out)
{
    const int row  = blockIdx.x;
    const int t    = threadIdx.x;
    const int lane = t & 31;
    const int warp = t >> 5;

    __shared__ float s_we[128];
    __shared__ float s_thr;
    __shared__ float s_red[4];
    __shared__ float s_part[4][NCLS];

    const float NEG_INF = -__int_as_float(0x7f800000);

    float v = (t < NEXP) ? we_l[row * NEXP + t] : NEG_INF;
    s_we[t] = v;
    __syncthreads();

    int n = n_experts[row];
    n = (n < NEXP) ? n : NEXP;

    if (t < NEXP) {
        int cgt = 0, ceq = 0;
#pragma unroll 4
        for (int j = 0; j < NEXP; j++) {
            float u = s_we[j];
            cgt += (u > v);
            ceq += (u == v);
        }
        if (cgt <= n - 1 && cgt + ceq > n - 1) s_thr = v;
    }
    __syncthreads();
    float thr = s_thr;

    float ewv = NEG_INF;
    if (t < NEXP && v >= thr) ewv = ew_l[row * NEXP + t];

    float m = ewv;
#pragma unroll
    for (int o = 16; o > 0; o >>= 1) m = fmaxf(m, __shfl_xor_sync(0xffffffffu, m, o));
    if (lane == 0) s_red[warp] = m;
    __syncthreads();
    m = fmaxf(fmaxf(s_red[0], s_red[1]), fmaxf(s_red[2], s_red[3]));
    __syncthreads();

    float e = expf(ewv - m);

    float se = e;
#pragma unroll
    for (int o = 16; o > 0; o >>= 1) se += __shfl_xor_sync(0xffffffffu, se, o);
    if (lane == 0) s_red[warp] = se;
    __syncthreads();
    se = s_red[0] + s_red[1] + s_red[2] + s_red[3];

    float part[NCLS];
#pragma unroll
    for (int c = 0; c < NCLS; c++) part[c] = 0.0f;
    if (t < NEXP) {
        float l[NCLS];
#pragma unroll
        for (int c = 0; c < NCLS; c++) l[c] = cls_l[row * NEC + t * NCLS + c];
        float mx = l[0];
#pragma unroll
        for (int c = 1; c < NCLS; c++) mx = fmaxf(mx, l[c]);
        float s = 0.0f;
#pragma unroll
        for (int c = 0; c < NCLS; c++) { l[c] = expf(l[c] - mx); s += l[c]; }
        float scale = e / s;
#pragma unroll
        for (int c = 0; c < NCLS; c++) part[c] = l[c] * scale;
    }

#pragma unroll
    for (int c = 0; c < NCLS; c++) {
        float p = part[c];
#pragma unroll
        for (int o = 16; o > 0; o >>= 1) p += __shfl_xor_sync(0xffffffffu, p, o);
        part[c] = p;
    }
    if (lane == 0)
#pragma unroll
        for (int c = 0; c < NCLS; c++) s_part[warp][c] = part[c];
    __syncthreads();

    if (t < NCLS) {
        float tot = s_part[0][t] + s_part[1][t] + s_part[2][t] + s_part[3][t];
        out[row * NCLS + t] = tot / se;
    }
}

// ---------------------------------------------------------------------------
// Launch
// ---------------------------------------------------------------------------
extern "C" void kernel_launch(void* const* d_in, const int* in_sizes, int n_in,
                              void* d_out, int out_size)
{
    const float* x      = (const float*)d_in[0];
    const int*   n_exp  = (const int*)  d_in[1];
    const float* cls_w1 = (const float*)d_in[2];
    const float* cls_b1 = (const float*)d_in[3];
    const float* cls_w2 = (const float*)d_in[4];
    const float* cls_b2 = (const float*)d_in[5];
    const float* we_w1  = (const float*)d_in[6];
    const float* we_b1  = (const float*)d_in[7];
    const float* we_w2  = (const float*)d_in[8];
    const float* we_b2  = (const float*)d_in[9];
    const float* ew_w1  = (const float*)d_in[10];
    const float* ew_b1  = (const float*)d_in[11];
    const float* ew_w2  = (const float*)d_in[12];
    const float* ew_b2  = (const float*)d_in[13];
    float* out = (float*)d_out;

    __nv_bfloat16 *xh, *xl;
    float *cls_lg, *we_lg, *ew_lg;
    cudaGetSymbolAddress((void**)&xh, g_xh);
    cudaGetSymbolAddress((void**)&xl, g_xl);
    cudaGetSymbolAddress((void**)&cls_lg, g_cls_logits);
    cudaGetSymbolAddress((void**)&we_lg,  g_we_logits);
    cudaGetSymbolAddress((void**)&ew_lg,  g_ew_logits);

    cudaFuncSetAttribute(fc1_merged,
                         cudaFuncAttributeMaxDynamicSharedMemorySize, SMEM_TOTAL);
    cudaFuncSetAttribute(fc2_merged,
                         cudaFuncAttributeMaxDynamicSharedMemorySize, SMEM_TOTAL);

    // 1) conversions
    convert_x_k<<<(BATCH * DIM) / 1024, 256>>>(x, xh, xl);
    dim3 tb(32, 8);
    wconv_all_k<<<dim3(DIM / 32, DIM / 32, 6), tb>>>(cls_w1, we_w1, ew_w1,
                                                     cls_w2, we_w2, ew_w2);

    // 2) fc1 merged (+gelu, split-bf16 output)
    fc1_merged<<<dim3(18, BATCH / 128), 512, SMEM_TOTAL>>>(cls_b1, we_b1, ew_b1);

    // 3) fc2 merged -> fp32 logits
    fc2_merged<<<dim3(8, BATCH / 128), 512, SMEM_TOTAL>>>(cls_b2, we_b2, ew_b2);

    // 4) row-wise softmax/topk epilogue
    epilogue_kernel<<<BATCH, 128>>>(we_lg, ew_lg, cls_lg, n_exp, out);
}

// round 15
// speedup vs baseline: 1.4051x; 1.4051x over previous
#include <cuda_runtime.h>
#include <cuda_bf16.h>
#include <math.h>
#include <stdint.h>

#define BATCH 16384
#define DIM   768
#define NEXP  124
#define NCLS  6
#define NEC   (NEXP * NCLS)   // 744
#define NECP  768             // padded N for cls fc2
#define NEXPP 128             // padded N for we/ew fc2

// ---------------------------------------------------------------------------
// Scratch (static device globals; allocation-free at runtime)
// ---------------------------------------------------------------------------
__device__ __nv_bfloat16 g_xh[BATCH * DIM];
__device__ __nv_bfloat16 g_xl[BATCH * DIM];
__device__ __nv_bfloat16 g_hh[3][BATCH * DIM];
__device__ __nv_bfloat16 g_hl[3][BATCH * DIM];
__device__ __nv_bfloat16 g_w1h[3][DIM * DIM];
__device__ __nv_bfloat16 g_w1l[3][DIM * DIM];
__device__ __nv_bfloat16 g_w2ch[NECP * DIM];
__device__ __nv_bfloat16 g_w2cl[NECP * DIM];
__device__ __nv_bfloat16 g_w2eh[2][NEXPP * DIM];
__device__ __nv_bfloat16 g_w2el[2][NEXPP * DIM];
__device__ float g_cls_logits[BATCH * NEC];
__device__ float g_we_logits[BATCH * NEXP];
__device__ float g_ew_logits[BATCH * NEXP];

// ---------------------------------------------------------------------------
// Portable (sm_80+) PTX helpers
// ---------------------------------------------------------------------------
__device__ __forceinline__ uint32_t smem_u32(const void* p) {
    uint32_t a;
    asm("{ .reg .u64 t; cvta.to.shared.u64 t, %1; cvt.u32.u64 %0, t; }"
        : "=r"(a) : "l"(p));
    return a;
}

__device__ __forceinline__ void cp_async16(uint32_t dst, const void* src) {
    asm volatile("cp.async.cg.shared.global [%0], [%1], 16;"
                 :: "r"(dst), "l"(src) : "memory");
}
__device__ __forceinline__ void cp_commit() {
    asm volatile("cp.async.commit_group;" ::: "memory");
}
__device__ __forceinline__ void cp_wait1() {
    asm volatile("cp.async.wait_group 1;" ::: "memory");
}

__device__ __forceinline__ void ldsm4(uint32_t* r, uint32_t addr) {
    asm volatile("ldmatrix.sync.aligned.m8n8.x4.shared.b16 {%0,%1,%2,%3}, [%4];"
                 : "=r"(r[0]), "=r"(r[1]), "=r"(r[2]), "=r"(r[3]) : "r"(addr));
}

// non-volatile: pure register semantics, lets ptxas schedule HMMA freely
__device__ __forceinline__ void mma_bf16(float* c, const uint32_t* a,
                                         uint32_t b0, uint32_t b1) {
    asm("mma.sync.aligned.m16n8k16.row.col.f32.bf16.bf16.f32 "
        "{%0,%1,%2,%3}, {%4,%5,%6,%7}, {%8,%9}, {%0,%1,%2,%3};"
        : "+f"(c[0]), "+f"(c[1]), "+f"(c[2]), "+f"(c[3])
        : "r"(a[0]), "r"(a[1]), "r"(a[2]), "r"(a[3]), "r"(b0), "r"(b1));
}

__device__ __forceinline__ float gelu_exact(float x) {
    return 0.5f * x * (1.0f + erff(x * 0.70710678118654752f));
}

// ---------------------------------------------------------------------------
// Merged prep: z = 0..5 -> weight conversion, z = 6 -> x conversion.
// grid (128, 96, 7), block (32, 8).
// ---------------------------------------------------------------------------
__global__ __launch_bounds__(256)
void prep_all_k(const float* __restrict__ x,
                const float* __restrict__ cls_w1, const float* __restrict__ we_w1,
                const float* __restrict__ ew_w1,  const float* __restrict__ cls_w2,
                const float* __restrict__ we_w2,  const float* __restrict__ ew_w2)
{
    const int z = blockIdx.z;
    const int tid = threadIdx.y * 32 + threadIdx.x;

    if (z == 6) {
        // x -> split bf16 (vectorized): 12288 blocks x 256 threads x 1 float4
        int blk = blockIdx.y * gridDim.x + blockIdx.x;     // 0..12287
        int i = blk * 256 + tid;                            // float4 index
        float4 v = ((const float4*)x)[i];
        __nv_bfloat162 h01, h23, l01, l23;
        h01.x = __float2bfloat16(v.x);
        h01.y = __float2bfloat16(v.y);
        h23.x = __float2bfloat16(v.z);
        h23.y = __float2bfloat16(v.w);
        l01.x = __float2bfloat16(v.x - __bfloat162float(h01.x));
        l01.y = __float2bfloat16(v.y - __bfloat162float(h01.y));
        l23.x = __float2bfloat16(v.z - __bfloat162float(h23.x));
        l23.y = __float2bfloat16(v.w - __bfloat162float(h23.y));
        uint2 ho, lo;
        ho.x = *(uint32_t*)&h01; ho.y = *(uint32_t*)&h23;
        lo.x = *(uint32_t*)&l01; lo.y = *(uint32_t*)&l23;
        *(uint2*)(g_xh + 4 * (size_t)i) = ho;
        *(uint2*)(g_xl + 4 * (size_t)i) = lo;
        return;
    }

    if (blockIdx.x >= 24 || blockIdx.y >= 24) return;
    const float* W; int Nsrc, Npad;
    __nv_bfloat16 *Th, *Tl;
    switch (z) {
    case 0: W = cls_w1; Nsrc = DIM;  Npad = DIM;   Th = g_w1h[0]; Tl = g_w1l[0]; break;
    case 1: W = we_w1;  Nsrc = DIM;  Npad = DIM;   Th = g_w1h[1]; Tl = g_w1l[1]; break;
    case 2: W = ew_w1;  Nsrc = DIM;  Npad = DIM;   Th = g_w1h[2]; Tl = g_w1l[2]; break;
    case 3: W = cls_w2; Nsrc = NEC;  Npad = NECP;  Th = g_w2ch;   Tl = g_w2cl;   break;
    case 4: W = we_w2;  Nsrc = NEXP; Npad = NEXPP; Th = g_w2eh[0]; Tl = g_w2el[0]; break;
    default:W = ew_w2;  Nsrc = NEXP; Npad = NEXPP; Th = g_w2eh[1]; Tl = g_w2el[1]; break;
    }
    int n0 = blockIdx.x * 32, k0 = blockIdx.y * 32;
    if (n0 >= Npad) return;
    __shared__ float tile[32][33];
    int tx = threadIdx.x, ty = threadIdx.y;
    for (int i = ty; i < 32; i += 8) {
        int n = n0 + tx;
        tile[i][tx] = (n < Nsrc) ? W[(size_t)(k0 + i) * Nsrc + n] : 0.0f;
    }
    __syncthreads();
    for (int i = ty; i < 32; i += 8) {
        float v = tile[tx][i];
        __nv_bfloat16 h = __float2bfloat16(v);
        size_t o = (size_t)(n0 + i) * DIM + (k0 + tx);
        Th[o] = h;
        Tl[o] = __float2bfloat16(v - __bfloat162float(h));
    }
}

// ---------------------------------------------------------------------------
// Split-bf16 GEMM core (HMMA), 512 threads, 16 warps (4m x 4n), warp tile
// 32x32, CTA tile 128x128, BK=64, 3-stage cp.async ring.  (R10-best config)
// ---------------------------------------------------------------------------
#define BK 64
#define NKSTAGE (DIM / BK)           // 12
#define TILE_B 16384                 // one 128x64 bf16 tile
#define STAGE_B (4 * TILE_B)         // Ah, Al, Bh, Bl  (64 KB)
#define NPIPE 3
#define SMEM_TOTAL (NPIPE * STAGE_B) // 196608

struct GemmOut {
    float* outF;               // mode 0
    __nv_bfloat16* outH;       // mode 1
    __nv_bfloat16* outL;       // mode 1
    const float* bias;
    int Nreal;
    int mode;
};

__device__ __forceinline__
void gemm_core(const __nv_bfloat16* __restrict__ Ah,
               const __nv_bfloat16* __restrict__ Al,
               const __nv_bfloat16* __restrict__ Bh,
               const __nv_bfloat16* __restrict__ Bl,
               const GemmOut& o, int m0, int n0, char* dyn)
{
    const int tid  = threadIdx.x;
    const int lane = tid & 31;
    const int wid  = tid >> 5;
    const uint32_t smem = smem_u32(dyn);

    const int wm = (wid >> 2) * 32;      // 0,32,64,96
    const int wn = (wid & 3) * 32;       // 0,32,64,96

    const int lr = lane & 7;
    const int aRowBase = wm + lr + 8 * ((lane >> 3) & 1);   // + 16*i
    const int aChunkSel = lane >> 4;
    const int bRowBase = wn + lr + 8 * (lane >> 4);         // + 16*jj
    const int bChunkSel = (lane >> 3) & 1;

    float acc[2][4][4];
#pragma unroll
    for (int i = 0; i < 2; i++)
#pragma unroll
        for (int j = 0; j < 4; j++)
#pragma unroll
            for (int r = 0; r < 4; r++) acc[i][j][r] = 0.0f;

    auto load_stage = [&](int s) {
        const int k0 = s * BK;
        const uint32_t sb = smem + (s % NPIPE) * STAGE_B;
#pragma unroll
        for (int it = 0; it < 2; ++it) {
            int idx = it * 512 + tid;     // 0..1023
            int row = idx >> 3;           // 0..127
            int ch  = idx & 7;            // 16B chunk
            uint32_t sw = (uint32_t)(row * 128 + ((ch ^ (row & 7)) << 4));
            size_t aoff = (size_t)(m0 + row) * DIM + k0 + ch * 8;
            size_t boff = (size_t)(n0 + row) * DIM + k0 + ch * 8;
            cp_async16(sb + 0 * TILE_B + sw, Ah + aoff);
            cp_async16(sb + 1 * TILE_B + sw, Al + aoff);
            cp_async16(sb + 2 * TILE_B + sw, Bh + boff);
            cp_async16(sb + 3 * TILE_B + sw, Bl + boff);
        }
        cp_commit();
    };

    load_stage(0);
    load_stage(1);

#pragma unroll 1
    for (int s = 0; s < NKSTAGE; ++s) {
        cp_wait1();
        __syncthreads();
        const uint32_t base = smem + (s % NPIPE) * STAGE_B;

        uint32_t ah[2][4], al[2][4], bh[2][4], bl[2][4];
        // kk=0 hi fragments issued FIRST (refill the tensor pipe ASAP);
        // the next-stage cp.async issue overlaps their in-flight latency.
#pragma unroll
        for (int i = 0; i < 2; ++i) {
            int r = aRowBase + 16 * i;
            uint32_t addr = base + (uint32_t)(r * 128)
                          + (uint32_t)(((aChunkSel ^ (r & 7)) << 4));
            ldsm4(ah[i], addr);
        }
#pragma unroll
        for (int jj = 0; jj < 2; ++jj) {
            int r = bRowBase + 16 * jj;
            uint32_t addr = base + 2 * TILE_B + (uint32_t)(r * 128)
                          + (uint32_t)(((bChunkSel ^ (r & 7)) << 4));
            ldsm4(bh[jj], addr);
        }
        if (s + 2 < NKSTAGE) load_stage(s + 2); else cp_commit();

#pragma unroll
        for (int kk = 0; kk < 4; ++kk) {
            if (kk > 0) {
#pragma unroll
                for (int i = 0; i < 2; ++i) {
                    int r = aRowBase + 16 * i;
                    uint32_t addr = base + (uint32_t)(r * 128)
                                  + (uint32_t)((((2 * kk + aChunkSel) ^ (r & 7)) << 4));
                    ldsm4(ah[i], addr);
                }
#pragma unroll
                for (int jj = 0; jj < 2; ++jj) {
                    int r = bRowBase + 16 * jj;
                    uint32_t addr = base + 2 * TILE_B + (uint32_t)(r * 128)
                                  + (uint32_t)((((2 * kk + bChunkSel) ^ (r & 7)) << 4));
                    ldsm4(bh[jj], addr);
                }
            }
            // hi x hi MMAs can start while lo fragments load
#pragma unroll
            for (int i = 0; i < 2; ++i)
#pragma unroll
                for (int j = 0; j < 4; ++j)
                    mma_bf16(acc[i][j], ah[i],
                             bh[j >> 1][(j & 1) * 2], bh[j >> 1][(j & 1) * 2 + 1]);
            // lo fragments
#pragma unroll
            for (int i = 0; i < 2; ++i) {
                int r = aRowBase + 16 * i;
                uint32_t addr = base + TILE_B + (uint32_t)(r * 128)
                              + (uint32_t)((((2 * kk + aChunkSel) ^ (r & 7)) << 4));
                ldsm4(al[i], addr);
            }
#pragma unroll
            for (int jj = 0; jj < 2; ++jj) {
                int r = bRowBase + 16 * jj;
                uint32_t addr = base + 3 * TILE_B + (uint32_t)(r * 128)
                              + (uint32_t)((((2 * kk + bChunkSel) ^ (r & 7)) << 4));
                ldsm4(bl[jj], addr);
            }
#pragma unroll
            for (int i = 0; i < 2; ++i)
#pragma unroll
                for (int j = 0; j < 4; ++j)
                    mma_bf16(acc[i][j], ah[i],
                             bl[j >> 1][(j & 1) * 2], bl[j >> 1][(j & 1) * 2 + 1]);
#pragma unroll
            for (int i = 0; i < 2; ++i)
#pragma unroll
                for (int j = 0; j < 4; ++j)
                    mma_bf16(acc[i][j], al[i],
                             bh[j >> 1][(j & 1) * 2], bh[j >> 1][(j & 1) * 2 + 1]);
        }
    }

    // ---- epilogue from registers ----
    const int qrow = lane >> 2;
    const int qcol = (lane & 3) * 2;
#pragma unroll
    for (int i = 0; i < 2; ++i) {
        int r0 = m0 + wm + 16 * i + qrow;
        int r1 = r0 + 8;
#pragma unroll
        for (int j = 0; j < 4; ++j) {
            int col = n0 + wn + j * 8 + qcol;
            if (o.mode == 1) {
                float2 bv = *(const float2*)(o.bias + col);
                float g0 = gelu_exact(acc[i][j][0] + bv.x);
                float g1 = gelu_exact(acc[i][j][1] + bv.y);
                float g2 = gelu_exact(acc[i][j][2] + bv.x);
                float g3 = gelu_exact(acc[i][j][3] + bv.y);
                __nv_bfloat162 h01, h23, l01, l23;
                h01.x = __float2bfloat16(g0); h01.y = __float2bfloat16(g1);
                h23.x = __float2bfloat16(g2); h23.y = __float2bfloat16(g3);
                l01.x = __float2bfloat16(g0 - __bfloat162float(h01.x));
                l01.y = __float2bfloat16(g1 - __bfloat162float(h01.y));
                l23.x = __float2bfloat16(g2 - __bfloat162float(h23.x));
                l23.y = __float2bfloat16(g3 - __bfloat162float(h23.y));
                *(__nv_bfloat162*)(o.outH + (size_t)r0 * DIM + col) = h01;
                *(__nv_bfloat162*)(o.outH + (size_t)r1 * DIM + col) = h23;
                *(__nv_bfloat162*)(o.outL + (size_t)r0 * DIM + col) = l01;
                *(__nv_bfloat162*)(o.outL + (size_t)r1 * DIM + col) = l23;
            } else {
                if (col < o.Nreal) {
                    float2 bv = *(const float2*)(o.bias + col);
                    float2 o0, o1;
                    o0.x = acc[i][j][0] + bv.x; o0.y = acc[i][j][1] + bv.y;
                    o1.x = acc[i][j][2] + bv.x; o1.y = acc[i][j][3] + bv.y;
                    *(float2*)(o.outF + (size_t)r0 * o.Nreal + col) = o0;
                    *(float2*)(o.outF + (size_t)r1 * o.Nreal + col) = o1;
                }
            }
        }
    }
}

// ---- merged fc1: grid (18, 128); layer = bx/6, n0 = (bx%6)*128 ----
__global__ __launch_bounds__(512, 1)
void fc1_merged(const float* __restrict__ b_cls, const float* __restrict__ b_we,
                const float* __restrict__ b_ew)
{
    extern __shared__ __align__(1024) char dyn[];
    const int bx = blockIdx.x;
    const int layer = bx / 6;
    const int n0 = (bx % 6) * 128;
    const int m0 = blockIdx.y * 128;
    GemmOut o;
    o.outF = nullptr;
    o.outH = g_hh[layer];
    o.outL = g_hl[layer];
    o.bias = (layer == 0) ? b_cls : (layer == 1) ? b_we : b_ew;
    o.Nreal = DIM;
    o.mode = 1;
    gemm_core(g_xh, g_xl, g_w1h[layer], g_w1l[layer], o, m0, n0, dyn);
}

// ---- merged fc2: grid (8, 128) ----
__global__ __launch_bounds__(512, 1)
void fc2_merged(const float* __restrict__ b_cls, const float* __restrict__ b_we,
                const float* __restrict__ b_ew)
{
    extern __shared__ __align__(1024) char dyn[];
    const int bx = blockIdx.x;
    const int m0 = blockIdx.y * 128;
    GemmOut o;
    o.outH = nullptr; o.outL = nullptr; o.mode = 0;
    const __nv_bfloat16 *Ah, *Al, *Bh, *Bl;
    int n0;
    if (bx < 6) {
        Ah = g_hh[0]; Al = g_hl[0]; Bh = g_w2ch; Bl = g_w2cl;
        o.outF = g_cls_logits; o.bias = b_cls; o.Nreal = NEC; n0 = bx * 128;
    } else if (bx == 6) {
        Ah = g_hh[1]; Al = g_hl[1]; Bh = g_w2eh[0]; Bl = g_w2el[0];
        o.outF = g_we_logits; o.bias = b_we; o.Nreal = NEXP; n0 = 0;
    } else {
        Ah = g_hh[2]; Al = g_hl[2]; Bh = g_w2eh[1]; Bl = g_w2el[1];
        o.outF = g_ew_logits; o.bias = b_ew; o.Nreal = NEXP; n0 = 0;
    }
    gemm_core(Ah, Al, Bh, Bl, o, m0, n0, dyn);
}

// ---------------------------------------------------------------------------
// Row-wise epilogue (unchanged, verified)
// ---------------------------------------------------------------------------
__global__ __launch_bounds__(128)
void epilogue_kernel(const float* __restrict__ we_l,
                     const float* __restrict__ ew_l,
                     const float* __restrict__ cls_l,
                     const int*   __restrict__ n_experts,
                     float* __restrict__ out)
{
    const int row  = blockIdx.x;
    const int t    = threadIdx.x;
    const int lane = t & 31;
    const int warp = t >> 5;

    __shared__ float s_we[128];
    __shared__ float s_thr;
    __shared__ float s_red[4];
    __shared__ float s_part[4][NCLS];

    const float NEG_INF = -__int_as_float(0x7f800000);

    float v = (t < NEXP) ? we_l[row * NEXP + t] : NEG_INF;
    s_we[t] = v;
    __syncthreads();

    int n = n_experts[row];
    n = (n < NEXP) ? n : NEXP;

    if (t < NEXP) {
        int cgt = 0, ceq = 0;
#pragma unroll 4
        for (int j = 0; j < NEXP; j++) {
            float u = s_we[j];
            cgt += (u > v);
            ceq += (u == v);
        }
        if (cgt <= n - 1 && cgt + ceq > n - 1) s_thr = v;
    }
    __syncthreads();
    float thr = s_thr;

    float ewv = NEG_INF;
    if (t < NEXP && v >= thr) ewv = ew_l[row * NEXP + t];

    float m = ewv;
#pragma unroll
    for (int o = 16; o > 0; o >>= 1) m = fmaxf(m, __shfl_xor_sync(0xffffffffu, m, o));
    if (lane == 0) s_red[warp] = m;
    __syncthreads();
    m = fmaxf(fmaxf(s_red[0], s_red[1]), fmaxf(s_red[2], s_red[3]));
    __syncthreads();

    float e = expf(ewv - m);

    float se = e;
#pragma unroll
    for (int o = 16; o > 0; o >>= 1) se += __shfl_xor_sync(0xffffffffu, se, o);
    if (lane == 0) s_red[warp] = se;
    __syncthreads();
    se = s_red[0] + s_red[1] + s_red[2] + s_red[3];

    float part[NCLS];
#pragma unroll
    for (int c = 0; c < NCLS; c++) part[c] = 0.0f;
    if (t < NEXP) {
        float l[NCLS];
#pragma unroll
        for (int c = 0; c < NCLS; c++) l[c] = cls_l[row * NEC + t * NCLS + c];
        float mx = l[0];
#pragma unroll
        for (int c = 1; c < NCLS; c++) mx = fmaxf(mx, l[c]);
        float s = 0.0f;
#pragma unroll
        for (int c = 0; c < NCLS; c++) { l[c] = expf(l[c] - mx); s += l[c]; }
        float scale = e / s;
#pragma unroll
        for (int c = 0; c < NCLS; c++) part[c] = l[c] * scale;
    }

#pragma unroll
    for (int c = 0; c < NCLS; c++) {
        float p = part[c];
#pragma unroll
        for (int o = 16; o > 0; o >>= 1) p += __shfl_xor_sync(0xffffffffu, p, o);
        part[c] = p;
    }
    if (lane == 0)
#pragma unroll
        for (int c = 0; c < NCLS; c++) s_part[warp][c] = part[c];
    __syncthreads();

    if (t < NCLS) {
        float tot = s_part[0][t] + s_part[1][t] + s_part[2][t] + s_part[3][t];
        out[row * NCLS + t] = tot / se;
    }
}

// ---------------------------------------------------------------------------
// Launch
// ---------------------------------------------------------------------------
extern "C" void kernel_launch(void* const* d_in, const int* in_sizes, int n_in,
                              void* d_out, int out_size)
{
    const float* x      = (const float*)d_in[0];
    const int*   n_exp  = (const int*)  d_in[1];
    const float* cls_w1 = (const float*)d_in[2];
    const float* cls_b1 = (const float*)d_in[3];
    const float* cls_w2 = (const float*)d_in[4];
    const float* cls_b2 = (const float*)d_in[5];
    const float* we_w1  = (const float*)d_in[6];
    const float* we_b1  = (const float*)d_in[7];
    const float* we_w2  = (const float*)d_in[8];
    const float* we_b2  = (const float*)d_in[9];
    const float* ew_w1  = (const float*)d_in[10];
    const float* ew_b1  = (const float*)d_in[11];
    const float* ew_w2  = (const float*)d_in[12];
    const float* ew_b2  = (const float*)d_in[13];
    float* out = (float*)d_out;

    float *cls_lg, *we_lg, *ew_lg;
    cudaGetSymbolAddress((void**)&cls_lg, g_cls_logits);
    cudaGetSymbolAddress((void**)&we_lg,  g_we_logits);
    cudaGetSymbolAddress((void**)&ew_lg,  g_ew_logits);

    cudaFuncSetAttribute(fc1_merged,
                         cudaFuncAttributeMaxDynamicSharedMemorySize, SMEM_TOTAL);
    cudaFuncSetAttribute(fc2_merged,
                         cudaFuncAttributeMaxDynamicSharedMemorySize, SMEM_TOTAL);

    // 1) merged conversions (x + all 6 weight matrices) in ONE launch
    dim3 tb(32, 8);
    prep_all_k<<<dim3(128, 96, 7), tb>>>(x, cls_w1, we_w1, ew_w1,
                                         cls_w2, we_w2, ew_w2);

    // 2) fc1 merged (+gelu, split-bf16 output)
    fc1_merged<<<dim3(18, BATCH / 128), 512, SMEM_TOTAL>>>(cls_b1, we_b1, ew_b1);

    // 3) fc2 merged -> fp32 logits
    fc2_merged<<<dim3(8, BATCH / 128), 512, SMEM_TOTAL>>>(cls_b2, we_b2, ew_b2);

    // 4) row-wise softmax/topk epilogue
    epilogue_kernel<<<BATCH, 128>>>(we_lg, ew_lg, cls_lg, n_exp, out);
}

// round 16
// speedup vs baseline: 1.5284x; 1.0877x over previous
#include <cuda_runtime.h>
#include <cuda_bf16.h>
#include <math.h>
#include <stdint.h>

#define BATCH 16384
#define DIM   768
#define NEXP  124
#define NCLS  6
#define NEC   (NEXP * NCLS)   // 744
#define NECP  768             // padded N for cls fc2
#define NEXPP 128             // padded N for we/ew fc2

// ---------------------------------------------------------------------------
// Scratch (static device globals; allocation-free at runtime)
// ---------------------------------------------------------------------------
__device__ __nv_bfloat16 g_xh[BATCH * DIM];
__device__ __nv_bfloat16 g_xl[BATCH * DIM];
__device__ __nv_bfloat16 g_hh[3][BATCH * DIM];
__device__ __nv_bfloat16 g_hl[3][BATCH * DIM];
__device__ __nv_bfloat16 g_w1h[3][DIM * DIM];
__device__ __nv_bfloat16 g_w1l[3][DIM * DIM];
__device__ __nv_bfloat16 g_w2ch[NECP * DIM];
__device__ __nv_bfloat16 g_w2cl[NECP * DIM];
__device__ __nv_bfloat16 g_w2eh[2][NEXPP * DIM];
__device__ __nv_bfloat16 g_w2el[2][NEXPP * DIM];
__device__ float g_cls_logits[BATCH * NEC];
__device__ float g_we_logits[BATCH * NEXP];
__device__ float g_ew_logits[BATCH * NEXP];

// ---------------------------------------------------------------------------
// Portable (sm_80+) PTX helpers
// ---------------------------------------------------------------------------
__device__ __forceinline__ uint32_t smem_u32(const void* p) {
    uint32_t a;
    asm("{ .reg .u64 t; cvta.to.shared.u64 t, %1; cvt.u32.u64 %0, t; }"
        : "=r"(a) : "l"(p));
    return a;
}

__device__ __forceinline__ void cp_async16(uint32_t dst, const void* src) {
    asm volatile("cp.async.cg.shared.global [%0], [%1], 16;"
                 :: "r"(dst), "l"(src) : "memory");
}
__device__ __forceinline__ void cp_commit() {
    asm volatile("cp.async.commit_group;" ::: "memory");
}
__device__ __forceinline__ void cp_wait1() {
    asm volatile("cp.async.wait_group 1;" ::: "memory");
}

__device__ __forceinline__ void ldsm4(uint32_t* r, uint32_t addr) {
    asm volatile("ldmatrix.sync.aligned.m8n8.x4.shared.b16 {%0,%1,%2,%3}, [%4];"
                 : "=r"(r[0]), "=r"(r[1]), "=r"(r[2]), "=r"(r[3]) : "r"(addr));
}

// non-volatile: pure register semantics, lets ptxas schedule HMMA freely
__device__ __forceinline__ void mma_bf16(float* c, const uint32_t* a,
                                         uint32_t b0, uint32_t b1) {
    asm("mma.sync.aligned.m16n8k16.row.col.f32.bf16.bf16.f32 "
        "{%0,%1,%2,%3}, {%4,%5,%6,%7}, {%8,%9}, {%0,%1,%2,%3};"
        : "+f"(c[0]), "+f"(c[1]), "+f"(c[2]), "+f"(c[3])
        : "r"(a[0]), "r"(a[1]), "r"(a[2]), "r"(a[3]), "r"(b0), "r"(b1));
}

__device__ __forceinline__ float gelu_exact(float x) {
    return 0.5f * x * (1.0f + erff(x * 0.70710678118654752f));
}

// ---------------------------------------------------------------------------
// Conversions (R10 configuration — separate launches)
// ---------------------------------------------------------------------------
__global__ __launch_bounds__(256)
void convert_x_k(const float* __restrict__ x,
                 __nv_bfloat16* __restrict__ xh, __nv_bfloat16* __restrict__ xl) {
    int i = blockIdx.x * blockDim.x + threadIdx.x;   // float4 index
    float4 v = ((const float4*)x)[i];
    __nv_bfloat162 h01, h23, l01, l23;
    h01.x = __float2bfloat16(v.x);
    h01.y = __float2bfloat16(v.y);
    h23.x = __float2bfloat16(v.z);
    h23.y = __float2bfloat16(v.w);
    l01.x = __float2bfloat16(v.x - __bfloat162float(h01.x));
    l01.y = __float2bfloat16(v.y - __bfloat162float(h01.y));
    l23.x = __float2bfloat16(v.z - __bfloat162float(h23.x));
    l23.y = __float2bfloat16(v.w - __bfloat162float(h23.y));
    uint2 ho, lo;
    ho.x = *(uint32_t*)&h01; ho.y = *(uint32_t*)&h23;
    lo.x = *(uint32_t*)&l01; lo.y = *(uint32_t*)&l23;
    *(uint2*)(xh + 4 * (size_t)i) = ho;
    *(uint2*)(xl + 4 * (size_t)i) = lo;
}

__global__ __launch_bounds__(256)
void wconv_all_k(const float* __restrict__ cls_w1, const float* __restrict__ we_w1,
                 const float* __restrict__ ew_w1,  const float* __restrict__ cls_w2,
                 const float* __restrict__ we_w2,  const float* __restrict__ ew_w2)
{
    const int z = blockIdx.z;
    const float* W; int Nsrc, Npad;
    __nv_bfloat16 *Th, *Tl;
    switch (z) {
    case 0: W = cls_w1; Nsrc = DIM;  Npad = DIM;   Th = g_w1h[0]; Tl = g_w1l[0]; break;
    case 1: W = we_w1;  Nsrc = DIM;  Npad = DIM;   Th = g_w1h[1]; Tl = g_w1l[1]; break;
    case 2: W = ew_w1;  Nsrc = DIM;  Npad = DIM;   Th = g_w1h[2]; Tl = g_w1l[2]; break;
    case 3: W = cls_w2; Nsrc = NEC;  Npad = NECP;  Th = g_w2ch;   Tl = g_w2cl;   break;
    case 4: W = we_w2;  Nsrc = NEXP; Npad = NEXPP; Th = g_w2eh[0]; Tl = g_w2el[0]; break;
    default:W = ew_w2;  Nsrc = NEXP; Npad = NEXPP; Th = g_w2eh[1]; Tl = g_w2el[1]; break;
    }
    int n0 = blockIdx.x * 32, k0 = blockIdx.y * 32;
    if (n0 >= Npad) return;
    __shared__ float tile[32][33];
    int tx = threadIdx.x, ty = threadIdx.y;
    for (int i = ty; i < 32; i += 8) {
        int n = n0 + tx;
        tile[i][tx] = (n < Nsrc) ? W[(size_t)(k0 + i) * Nsrc + n] : 0.0f;
    }
    __syncthreads();
    for (int i = ty; i < 32; i += 8) {
        float v = tile[tx][i];
        __nv_bfloat16 h = __float2bfloat16(v);
        size_t o = (size_t)(n0 + i) * DIM + (k0 + tx);
        Th[o] = h;
        Tl[o] = __float2bfloat16(v - __bfloat162float(h));
    }
}

// ---------------------------------------------------------------------------
// Split-bf16 GEMM core (HMMA), 512 threads, 16 warps (4m x 4n), warp tile
// 32x32, CTA tile 128x128, BK=64, 3-stage cp.async ring.  (R10-best config)
// ---------------------------------------------------------------------------
#define BK 64
#define NKSTAGE (DIM / BK)           // 12
#define TILE_B 16384                 // one 128x64 bf16 tile
#define STAGE_B (4 * TILE_B)         // Ah, Al, Bh, Bl  (64 KB)
#define NPIPE 3
#define SMEM_TOTAL (NPIPE * STAGE_B) // 196608

struct GemmOut {
    float* outF;               // mode 0
    __nv_bfloat16* outH;       // mode 1
    __nv_bfloat16* outL;       // mode 1
    const float* bias;
    int Nreal;
    int mode;
};

__device__ __forceinline__
void gemm_core(const __nv_bfloat16* __restrict__ Ah,
               const __nv_bfloat16* __restrict__ Al,
               const __nv_bfloat16* __restrict__ Bh,
               const __nv_bfloat16* __restrict__ Bl,
               const GemmOut& o, int m0, int n0, char* dyn)
{
    const int tid  = threadIdx.x;
    const int lane = tid & 31;
    const int wid  = tid >> 5;
    const uint32_t smem = smem_u32(dyn);

    const int wm = (wid >> 2) * 32;      // 0,32,64,96
    const int wn = (wid & 3) * 32;       // 0,32,64,96

    const int lr = lane & 7;
    const int aRowBase = wm + lr + 8 * ((lane >> 3) & 1);   // + 16*i
    const int aChunkSel = lane >> 4;
    const int bRowBase = wn + lr + 8 * (lane >> 4);         // + 16*jj
    const int bChunkSel = (lane >> 3) & 1;

    float acc[2][4][4];
#pragma unroll
    for (int i = 0; i < 2; i++)
#pragma unroll
        for (int j = 0; j < 4; j++)
#pragma unroll
            for (int r = 0; r < 4; r++) acc[i][j][r] = 0.0f;

    auto load_stage = [&](int s) {
        const int k0 = s * BK;
        const uint32_t sb = smem + (s % NPIPE) * STAGE_B;
#pragma unroll
        for (int it = 0; it < 2; ++it) {
            int idx = it * 512 + tid;     // 0..1023
            int row = idx >> 3;           // 0..127
            int ch  = idx & 7;            // 16B chunk
            uint32_t sw = (uint32_t)(row * 128 + ((ch ^ (row & 7)) << 4));
            size_t aoff = (size_t)(m0 + row) * DIM + k0 + ch * 8;
            size_t boff = (size_t)(n0 + row) * DIM + k0 + ch * 8;
            cp_async16(sb + 0 * TILE_B + sw, Ah + aoff);
            cp_async16(sb + 1 * TILE_B + sw, Al + aoff);
            cp_async16(sb + 2 * TILE_B + sw, Bh + boff);
            cp_async16(sb + 3 * TILE_B + sw, Bl + boff);
        }
        cp_commit();
    };

    load_stage(0);
    load_stage(1);

#pragma unroll 1
    for (int s = 0; s < NKSTAGE; ++s) {
        cp_wait1();
        __syncthreads();
        const uint32_t base = smem + (s % NPIPE) * STAGE_B;

        uint32_t ah[2][4], al[2][4], bh[2][4], bl[2][4];
        // kk=0 hi fragments issued FIRST (refill the tensor pipe ASAP);
        // the next-stage cp.async issue overlaps their in-flight latency.
#pragma unroll
        for (int i = 0; i < 2; ++i) {
            int r = aRowBase + 16 * i;
            uint32_t addr = base + (uint32_t)(r * 128)
                          + (uint32_t)(((aChunkSel ^ (r & 7)) << 4));
            ldsm4(ah[i], addr);
        }
#pragma unroll
        for (int jj = 0; jj < 2; ++jj) {
            int r = bRowBase + 16 * jj;
            uint32_t addr = base + 2 * TILE_B + (uint32_t)(r * 128)
                          + (uint32_t)(((bChunkSel ^ (r & 7)) << 4));
            ldsm4(bh[jj], addr);
        }
        if (s + 2 < NKSTAGE) load_stage(s + 2); else cp_commit();

#pragma unroll
        for (int kk = 0; kk < 4; ++kk) {
            if (kk > 0) {
#pragma unroll
                for (int i = 0; i < 2; ++i) {
                    int r = aRowBase + 16 * i;
                    uint32_t addr = base + (uint32_t)(r * 128)
                                  + (uint32_t)((((2 * kk + aChunkSel) ^ (r & 7)) << 4));
                    ldsm4(ah[i], addr);
                }
#pragma unroll
                for (int jj = 0; jj < 2; ++jj) {
                    int r = bRowBase + 16 * jj;
                    uint32_t addr = base + 2 * TILE_B + (uint32_t)(r * 128)
                                  + (uint32_t)((((2 * kk + bChunkSel) ^ (r & 7)) << 4));
                    ldsm4(bh[jj], addr);
                }
            }
            // hi x hi MMAs can start while lo fragments load
#pragma unroll
            for (int i = 0; i < 2; ++i)
#pragma unroll
                for (int j = 0; j < 4; ++j)
                    mma_bf16(acc[i][j], ah[i],
                             bh[j >> 1][(j & 1) * 2], bh[j >> 1][(j & 1) * 2 + 1]);
            // lo fragments
#pragma unroll
            for (int i = 0; i < 2; ++i) {
                int r = aRowBase + 16 * i;
                uint32_t addr = base + TILE_B + (uint32_t)(r * 128)
                              + (uint32_t)((((2 * kk + aChunkSel) ^ (r & 7)) << 4));
                ldsm4(al[i], addr);
            }
#pragma unroll
            for (int jj = 0; jj < 2; ++jj) {
                int r = bRowBase + 16 * jj;
                uint32_t addr = base + 3 * TILE_B + (uint32_t)(r * 128)
                              + (uint32_t)((((2 * kk + bChunkSel) ^ (r & 7)) << 4));
                ldsm4(bl[jj], addr);
            }
#pragma unroll
            for (int i = 0; i < 2; ++i)
#pragma unroll
                for (int j = 0; j < 4; ++j)
                    mma_bf16(acc[i][j], ah[i],
                             bl[j >> 1][(j & 1) * 2], bl[j >> 1][(j & 1) * 2 + 1]);
#pragma unroll
            for (int i = 0; i < 2; ++i)
#pragma unroll
                for (int j = 0; j < 4; ++j)
                    mma_bf16(acc[i][j], al[i],
                             bh[j >> 1][(j & 1) * 2], bh[j >> 1][(j & 1) * 2 + 1]);
        }
    }

    // ---- epilogue from registers ----
    const int qrow = lane >> 2;
    const int qcol = (lane & 3) * 2;
#pragma unroll
    for (int i = 0; i < 2; ++i) {
        int r0 = m0 + wm + 16 * i + qrow;
        int r1 = r0 + 8;
#pragma unroll
        for (int j = 0; j < 4; ++j) {
            int col = n0 + wn + j * 8 + qcol;
            if (o.mode == 1) {
                float2 bv = *(const float2*)(o.bias + col);
                float g0 = gelu_exact(acc[i][j][0] + bv.x);
                float g1 = gelu_exact(acc[i][j][1] + bv.y);
                float g2 = gelu_exact(acc[i][j][2] + bv.x);
                float g3 = gelu_exact(acc[i][j][3] + bv.y);
                __nv_bfloat162 h01, h23, l01, l23;
                h01.x = __float2bfloat16(g0); h01.y = __float2bfloat16(g1);
                h23.x = __float2bfloat16(g2); h23.y = __float2bfloat16(g3);
                l01.x = __float2bfloat16(g0 - __bfloat162float(h01.x));
                l01.y = __float2bfloat16(g1 - __bfloat162float(h01.y));
                l23.x = __float2bfloat16(g2 - __bfloat162float(h23.x));
                l23.y = __float2bfloat16(g3 - __bfloat162float(h23.y));
                *(__nv_bfloat162*)(o.outH + (size_t)r0 * DIM + col) = h01;
                *(__nv_bfloat162*)(o.outH + (size_t)r1 * DIM + col) = h23;
                *(__nv_bfloat162*)(o.outL + (size_t)r0 * DIM + col) = l01;
                *(__nv_bfloat162*)(o.outL + (size_t)r1 * DIM + col) = l23;
            } else {
                if (col < o.Nreal) {
                    float2 bv = *(const float2*)(o.bias + col);
                    float2 o0, o1;
                    o0.x = acc[i][j][0] + bv.x; o0.y = acc[i][j][1] + bv.y;
                    o1.x = acc[i][j][2] + bv.x; o1.y = acc[i][j][3] + bv.y;
                    *(float2*)(o.outF + (size_t)r0 * o.Nreal + col) = o0;
                    *(float2*)(o.outF + (size_t)r1 * o.Nreal + col) = o1;
                }
            }
        }
    }
}

// ---- merged fc1: grid (18, 128); layer = bx/6, n0 = (bx%6)*128 ----
__global__ __launch_bounds__(512, 1)
void fc1_merged(const float* __restrict__ b_cls, const float* __restrict__ b_we,
                const float* __restrict__ b_ew)
{
    extern __shared__ __align__(1024) char dyn[];
    const int bx = blockIdx.x;
    const int layer = bx / 6;
    const int n0 = (bx % 6) * 128;
    const int m0 = blockIdx.y * 128;
    GemmOut o;
    o.outF = nullptr;
    o.outH = g_hh[layer];
    o.outL = g_hl[layer];
    o.bias = (layer == 0) ? b_cls : (layer == 1) ? b_we : b_ew;
    o.Nreal = DIM;
    o.mode = 1;
    gemm_core(g_xh, g_xl, g_w1h[layer], g_w1l[layer], o, m0, n0, dyn);
}

// ---- merged fc2: grid (8, 128) ----
__global__ __launch_bounds__(512, 1)
void fc2_merged(const float* __restrict__ b_cls, const float* __restrict__ b_we,
                const float* __restrict__ b_ew)
{
    extern __shared__ __align__(1024) char dyn[];
    const int bx = blockIdx.x;
    const int m0 = blockIdx.y * 128;
    GemmOut o;
    o.outH = nullptr; o.outL = nullptr; o.mode = 0;
    const __nv_bfloat16 *Ah, *Al, *Bh, *Bl;
    int n0;
    if (bx < 6) {
        Ah = g_hh[0]; Al = g_hl[0]; Bh = g_w2ch; Bl = g_w2cl;
        o.outF = g_cls_logits; o.bias = b_cls; o.Nreal = NEC; n0 = bx * 128;
    } else if (bx == 6) {
        Ah = g_hh[1]; Al = g_hl[1]; Bh = g_w2eh[0]; Bl = g_w2el[0];
        o.outF = g_we_logits; o.bias = b_we; o.Nreal = NEXP; n0 = 0;
    } else {
        Ah = g_hh[2]; Al = g_hl[2]; Bh = g_w2eh[1]; Bl = g_w2el[1];
        o.outF = g_ew_logits; o.bias = b_ew; o.Nreal = NEXP; n0 = 0;
    }
    gemm_core(Ah, Al, Bh, Bl, o, m0, n0, dyn);
}

// ---------------------------------------------------------------------------
// Row-wise epilogue — optimized rank count (float4 LDS, dual-pipe counters)
// and __expf softmaxes. Threshold logic semantics unchanged.
// ---------------------------------------------------------------------------
__global__ __launch_bounds__(128)
void epilogue_kernel(const float* __restrict__ we_l,
                     const float* __restrict__ ew_l,
                     const float* __restrict__ cls_l,
                     const int*   __restrict__ n_experts,
                     float* __restrict__ out)
{
    const int row  = blockIdx.x;
    const int t    = threadIdx.x;
    const int lane = t & 31;
    const int warp = t >> 5;

    __shared__ __align__(16) float s_we[128];
    __shared__ float s_thr;
    __shared__ float s_red[4];
    __shared__ float s_part[4][NCLS];

    const float NEG_INF = -__int_as_float(0x7f800000);

    float v = (t < NEXP) ? we_l[row * NEXP + t] : NEG_INF;
    s_we[t] = v;
    __syncthreads();

    int n = n_experts[row];
    n = (n < NEXP) ? n : NEXP;

    // rank count: fgt on FMA pipe (float adds), ceq on ALU pipe (int adds);
    // float4 loads cut LDS count 4x. Counts <= 124 are exact in fp32.
    {
        float fgt = 0.0f;
        int ceq = 0;
#pragma unroll
        for (int j = 0; j < NEXP; j += 4) {
            float4 u4 = *(const float4*)&s_we[j];
            fgt += (u4.x > v) ? 1.0f : 0.0f;  ceq += (u4.x == v);
            fgt += (u4.y > v) ? 1.0f : 0.0f;  ceq += (u4.y == v);
            fgt += (u4.z > v) ? 1.0f : 0.0f;  ceq += (u4.z == v);
            fgt += (u4.w > v) ? 1.0f : 0.0f;  ceq += (u4.w == v);
        }
        int cgt = (int)fgt;
        if (t < NEXP && cgt <= n - 1 && cgt + ceq > n - 1) s_thr = v;  // rank n-1
    }
    __syncthreads();
    float thr = s_thr;

    float ewv = NEG_INF;
    if (t < NEXP && v >= thr) ewv = ew_l[row * NEXP + t];

    float m = ewv;
#pragma unroll
    for (int o = 16; o > 0; o >>= 1) m = fmaxf(m, __shfl_xor_sync(0xffffffffu, m, o));
    if (lane == 0) s_red[warp] = m;
    __syncthreads();
    m = fmaxf(fmaxf(s_red[0], s_red[1]), fmaxf(s_red[2], s_red[3]));
    __syncthreads();

    float e = (ewv == NEG_INF) ? 0.0f : __expf(ewv - m);

    float se = e;
#pragma unroll
    for (int o = 16; o > 0; o >>= 1) se += __shfl_xor_sync(0xffffffffu, se, o);
    if (lane == 0) s_red[warp] = se;
    __syncthreads();
    se = s_red[0] + s_red[1] + s_red[2] + s_red[3];

    float part[NCLS];
#pragma unroll
    for (int c = 0; c < NCLS; c++) part[c] = 0.0f;
    if (t < NEXP) {
        float l[NCLS];
#pragma unroll
        for (int c = 0; c < NCLS; c++) l[c] = cls_l[row * NEC + t * NCLS + c];
        float mx = l[0];
#pragma unroll
        for (int c = 1; c < NCLS; c++) mx = fmaxf(mx, l[c]);
        float s = 0.0f;
#pragma unroll
        for (int c = 0; c < NCLS; c++) { l[c] = __expf(l[c] - mx); s += l[c]; }
        float scale = e / s;
#pragma unroll
        for (int c = 0; c < NCLS; c++) part[c] = l[c] * scale;
    }

#pragma unroll
    for (int c = 0; c < NCLS; c++) {
        float p = part[c];
#pragma unroll
        for (int o = 16; o > 0; o >>= 1) p += __shfl_xor_sync(0xffffffffu, p, o);
        part[c] = p;
    }
    if (lane == 0)
#pragma unroll
        for (int c = 0; c < NCLS; c++) s_part[warp][c] = part[c];
    __syncthreads();

    if (t < NCLS) {
        float tot = s_part[0][t] + s_part[1][t] + s_part[2][t] + s_part[3][t];
        out[row * NCLS + t] = tot / se;
    }
}

// ---------------------------------------------------------------------------
// Launch
// ---------------------------------------------------------------------------
extern "C" void kernel_launch(void* const* d_in, const int* in_sizes, int n_in,
                              void* d_out, int out_size)
{
    const float* x      = (const float*)d_in[0];
    const int*   n_exp  = (const int*)  d_in[1];
    const float* cls_w1 = (const float*)d_in[2];
    const float* cls_b1 = (const float*)d_in[3];
    const float* cls_w2 = (const float*)d_in[4];
    const float* cls_b2 = (const float*)d_in[5];
    const float* we_w1  = (const float*)d_in[6];
    const float* we_b1  = (const float*)d_in[7];
    const float* we_w2  = (const float*)d_in[8];
    const float* we_b2  = (const float*)d_in[9];
    const float* ew_w1  = (const float*)d_in[10];
    const float* ew_b1  = (const float*)d_in[11];
    const float* ew_w2  = (const float*)d_in[12];
    const float* ew_b2  = (const float*)d_in[13];
    float* out = (float*)d_out;

    __nv_bfloat16 *xh, *xl;
    float *cls_lg, *we_lg, *ew_lg;
    cudaGetSymbolAddress((void**)&xh, g_xh);
    cudaGetSymbolAddress((void**)&xl, g_xl);
    cudaGetSymbolAddress((void**)&cls_lg, g_cls_logits);
    cudaGetSymbolAddress((void**)&we_lg,  g_we_logits);
    cudaGetSymbolAddress((void**)&ew_lg,  g_ew_logits);

    cudaFuncSetAttribute(fc1_merged,
                         cudaFuncAttributeMaxDynamicSharedMemorySize, SMEM_TOTAL);
    cudaFuncSetAttribute(fc2_merged,
                         cudaFuncAttributeMaxDynamicSharedMemorySize, SMEM_TOTAL);

    // 1) conversions (R10 configuration)
    convert_x_k<<<(BATCH * DIM) / 1024, 256>>>(x, xh, xl);
    dim3 tb(32, 8);
    wconv_all_k<<<dim3(DIM / 32, DIM / 32, 6), tb>>>(cls_w1, we_w1, ew_w1,
                                                     cls_w2, we_w2, ew_w2);

    // 2) fc1 merged (+gelu, split-bf16 output)
    fc1_merged<<<dim3(18, BATCH / 128), 512, SMEM_TOTAL>>>(cls_b1, we_b1, ew_b1);

    // 3) fc2 merged -> fp32 logits
    fc2_merged<<<dim3(8, BATCH / 128), 512, SMEM_TOTAL>>>(cls_b2, we_b2, ew_b2);

    // 4) row-wise softmax/topk epilogue
    epilogue_kernel<<<BATCH, 128>>>(we_lg, ew_lg, cls_lg, n_exp, out);
}

// round 17
// speedup vs baseline: 1.5344x; 1.0040x over previous
#include <cuda_runtime.h>
#include <cuda_bf16.h>
#include <math.h>
#include <stdint.h>

#define BATCH 16384
#define DIM   768
#define NEXP  124
#define NCLS  6
#define NEC   (NEXP * NCLS)   // 744
#define NECP  768             // padded N for cls fc2
#define NEXPP 128             // padded N for we/ew fc2

// ---------------------------------------------------------------------------
// Scratch (static device globals; allocation-free at runtime)
// ---------------------------------------------------------------------------
__device__ __nv_bfloat16 g_xh[BATCH * DIM];
__device__ __nv_bfloat16 g_xl[BATCH * DIM];
__device__ __nv_bfloat16 g_hh[3][BATCH * DIM];
__device__ __nv_bfloat16 g_hl[3][BATCH * DIM];
__device__ __nv_bfloat16 g_w1h[3][DIM * DIM];
__device__ __nv_bfloat16 g_w1l[3][DIM * DIM];
__device__ __nv_bfloat16 g_w2ch[NECP * DIM];
__device__ __nv_bfloat16 g_w2cl[NECP * DIM];
__device__ __nv_bfloat16 g_w2eh[2][NEXPP * DIM];
__device__ __nv_bfloat16 g_w2el[2][NEXPP * DIM];
__device__ float g_cls_logits[BATCH * NEC];
__device__ float g_we_logits[BATCH * NEXP];
__device__ float g_ew_logits[BATCH * NEXP];

// ---------------------------------------------------------------------------
// Portable (sm_80+) PTX helpers
// ---------------------------------------------------------------------------
__device__ __forceinline__ uint32_t smem_u32(const void* p) {
    uint32_t a;
    asm("{ .reg .u64 t; cvta.to.shared.u64 t, %1; cvt.u32.u64 %0, t; }"
        : "=r"(a) : "l"(p));
    return a;
}

__device__ __forceinline__ void cp_async16(uint32_t dst, const void* src) {
    asm volatile("cp.async.cg.shared.global [%0], [%1], 16;"
                 :: "r"(dst), "l"(src) : "memory");
}
__device__ __forceinline__ void cp_commit() {
    asm volatile("cp.async.commit_group;" ::: "memory");
}
__device__ __forceinline__ void cp_wait1() {
    asm volatile("cp.async.wait_group 1;" ::: "memory");
}

__device__ __forceinline__ void ldsm4(uint32_t* r, uint32_t addr) {
    asm volatile("ldmatrix.sync.aligned.m8n8.x4.shared.b16 {%0,%1,%2,%3}, [%4];"
                 : "=r"(r[0]), "=r"(r[1]), "=r"(r[2]), "=r"(r[3]) : "r"(addr));
}

// non-volatile: pure register semantics, lets ptxas schedule HMMA freely
__device__ __forceinline__ void mma_bf16(float* c, const uint32_t* a,
                                         uint32_t b0, uint32_t b1) {
    asm("mma.sync.aligned.m16n8k16.row.col.f32.bf16.bf16.f32 "
        "{%0,%1,%2,%3}, {%4,%5,%6,%7}, {%8,%9}, {%0,%1,%2,%3};"
        : "+f"(c[0]), "+f"(c[1]), "+f"(c[2]), "+f"(c[3])
        : "r"(a[0]), "r"(a[1]), "r"(a[2]), "r"(a[3]), "r"(b0), "r"(b1));
}

__device__ __forceinline__ float gelu_exact(float x) {
    return 0.5f * x * (1.0f + erff(x * 0.70710678118654752f));
}

// ---------------------------------------------------------------------------
// Merged prep, flat grid — blocks [0,12288): x conversion (one float4 per
// thread); blocks [12288,15744): weight conversion (zero wasted blocks).
// block = (32,8) = 256 threads.
// ---------------------------------------------------------------------------
#define XBLOCKS 12288                 // (BATCH*DIM/4) / 256
#define WBLK_PER 576                  // 24 x 24 tiles per weight matrix
#define PREP_BLOCKS (XBLOCKS + 6 * WBLK_PER)   // 15744

__global__ __launch_bounds__(256)
void prep_all_k(const float* __restrict__ x,
                const float* __restrict__ cls_w1, const float* __restrict__ we_w1,
                const float* __restrict__ ew_w1,  const float* __restrict__ cls_w2,
                const float* __restrict__ we_w2,  const float* __restrict__ ew_w2)
{
    const int tid = threadIdx.y * 32 + threadIdx.x;
    const int blk = blockIdx.x;

    if (blk < XBLOCKS) {
        int i = blk * 256 + tid;          // float4 index
        float4 v = ((const float4*)x)[i];
        __nv_bfloat162 h01, h23, l01, l23;
        h01.x = __float2bfloat16(v.x);
        h01.y = __float2bfloat16(v.y);
        h23.x = __float2bfloat16(v.z);
        h23.y = __float2bfloat16(v.w);
        l01.x = __float2bfloat16(v.x - __bfloat162float(h01.x));
        l01.y = __float2bfloat16(v.y - __bfloat162float(h01.y));
        l23.x = __float2bfloat16(v.z - __bfloat162float(h23.x));
        l23.y = __float2bfloat16(v.w - __bfloat162float(h23.y));
        uint2 ho, lo;
        ho.x = *(uint32_t*)&h01; ho.y = *(uint32_t*)&h23;
        lo.x = *(uint32_t*)&l01; lo.y = *(uint32_t*)&l23;
        *(uint2*)(g_xh + 4 * (size_t)i) = ho;
        *(uint2*)(g_xl + 4 * (size_t)i) = lo;
        return;
    }

    const int w = blk - XBLOCKS;          // 0..3455
    const int z = w / WBLK_PER;           // which weight matrix
    const int rem = w % WBLK_PER;
    const int n0 = (rem % 24) * 32;
    const int k0 = (rem / 24) * 32;

    const float* W; int Nsrc, Npad;
    __nv_bfloat16 *Th, *Tl;
    switch (z) {
    case 0: W = cls_w1; Nsrc = DIM;  Npad = DIM;   Th = g_w1h[0]; Tl = g_w1l[0]; break;
    case 1: W = we_w1;  Nsrc = DIM;  Npad = DIM;   Th = g_w1h[1]; Tl = g_w1l[1]; break;
    case 2: W = ew_w1;  Nsrc = DIM;  Npad = DIM;   Th = g_w1h[2]; Tl = g_w1l[2]; break;
    case 3: W = cls_w2; Nsrc = NEC;  Npad = NECP;  Th = g_w2ch;   Tl = g_w2cl;   break;
    case 4: W = we_w2;  Nsrc = NEXP; Npad = NEXPP; Th = g_w2eh[0]; Tl = g_w2el[0]; break;
    default:W = ew_w2;  Nsrc = NEXP; Npad = NEXPP; Th = g_w2eh[1]; Tl = g_w2el[1]; break;
    }
    if (n0 >= Npad) return;
    __shared__ float tile[32][33];
    int tx = threadIdx.x, ty = threadIdx.y;
    for (int i = ty; i < 32; i += 8) {
        int n = n0 + tx;
        tile[i][tx] = (n < Nsrc) ? W[(size_t)(k0 + i) * Nsrc + n] : 0.0f;
    }
    __syncthreads();
    for (int i = ty; i < 32; i += 8) {
        float v = tile[tx][i];
        __nv_bfloat16 h = __float2bfloat16(v);
        size_t o = (size_t)(n0 + i) * DIM + (k0 + tx);
        Th[o] = h;
        Tl[o] = __float2bfloat16(v - __bfloat162float(h));
    }
}

// ---------------------------------------------------------------------------
// Split-bf16 GEMM core (HMMA), 512 threads, 16 warps (4m x 4n), warp tile
// 32x32, CTA tile 128x128, BK=64, 3-stage cp.async ring.  (R10-best config)
// ---------------------------------------------------------------------------
#define BK 64
#define NKSTAGE (DIM / BK)           // 12
#define TILE_B 16384                 // one 128x64 bf16 tile
#define STAGE_B (4 * TILE_B)         // Ah, Al, Bh, Bl  (64 KB)
#define NPIPE 3
#define SMEM_TOTAL (NPIPE * STAGE_B) // 196608

struct GemmOut {
    float* outF;               // mode 0
    __nv_bfloat16* outH;       // mode 1
    __nv_bfloat16* outL;       // mode 1
    const float* bias;
    int Nreal;
    int mode;
};

__device__ __forceinline__
void gemm_core(const __nv_bfloat16* __restrict__ Ah,
               const __nv_bfloat16* __restrict__ Al,
               const __nv_bfloat16* __restrict__ Bh,
               const __nv_bfloat16* __restrict__ Bl,
               const GemmOut& o, int m0, int n0, char* dyn)
{
    const int tid  = threadIdx.x;
    const int lane = tid & 31;
    const int wid  = tid >> 5;
    const uint32_t smem = smem_u32(dyn);

    const int wm = (wid >> 2) * 32;      // 0,32,64,96
    const int wn = (wid & 3) * 32;       // 0,32,64,96

    const int lr = lane & 7;
    const int aRowBase = wm + lr + 8 * ((lane >> 3) & 1);   // + 16*i
    const int aChunkSel = lane >> 4;
    const int bRowBase = wn + lr + 8 * (lane >> 4);         // + 16*jj
    const int bChunkSel = (lane >> 3) & 1;

    float acc[2][4][4];
#pragma unroll
    for (int i = 0; i < 2; i++)
#pragma unroll
        for (int j = 0; j < 4; j++)
#pragma unroll
            for (int r = 0; r < 4; r++) acc[i][j][r] = 0.0f;

    auto load_stage = [&](int s) {
        const int k0 = s * BK;
        const uint32_t sb = smem + (s % NPIPE) * STAGE_B;
#pragma unroll
        for (int it = 0; it < 2; ++it) {
            int idx = it * 512 + tid;     // 0..1023
            int row = idx >> 3;           // 0..127
            int ch  = idx & 7;            // 16B chunk
            uint32_t sw = (uint32_t)(row * 128 + ((ch ^ (row & 7)) << 4));
            size_t aoff = (size_t)(m0 + row) * DIM + k0 + ch * 8;
            size_t boff = (size_t)(n0 + row) * DIM + k0 + ch * 8;
            cp_async16(sb + 0 * TILE_B + sw, Ah + aoff);
            cp_async16(sb + 1 * TILE_B + sw, Al + aoff);
            cp_async16(sb + 2 * TILE_B + sw, Bh + boff);
            cp_async16(sb + 3 * TILE_B + sw, Bl + boff);
        }
        cp_commit();
    };

    load_stage(0);
    load_stage(1);

#pragma unroll 1
    for (int s = 0; s < NKSTAGE; ++s) {
        cp_wait1();
        __syncthreads();
        const uint32_t base = smem + (s % NPIPE) * STAGE_B;

        uint32_t ah[2][4], al[2][4], bh[2][4], bl[2][4];
        // kk=0 hi fragments issued FIRST (refill the tensor pipe ASAP);
        // the next-stage cp.async issue overlaps their in-flight latency.
#pragma unroll
        for (int i = 0; i < 2; ++i) {
            int r = aRowBase + 16 * i;
            uint32_t addr = base + (uint32_t)(r * 128)
                          + (uint32_t)(((aChunkSel ^ (r & 7)) << 4));
            ldsm4(ah[i], addr);
        }
#pragma unroll
        for (int jj = 0; jj < 2; ++jj) {
            int r = bRowBase + 16 * jj;
            uint32_t addr = base + 2 * TILE_B + (uint32_t)(r * 128)
                          + (uint32_t)(((bChunkSel ^ (r & 7)) << 4));
            ldsm4(bh[jj], addr);
        }
        if (s + 2 < NKSTAGE) load_stage(s + 2); else cp_commit();

#pragma unroll
        for (int kk = 0; kk < 4; ++kk) {
            if (kk > 0) {
#pragma unroll
                for (int i = 0; i < 2; ++i) {
                    int r = aRowBase + 16 * i;
                    uint32_t addr = base + (uint32_t)(r * 128)
                                  + (uint32_t)((((2 * kk + aChunkSel) ^ (r & 7)) << 4));
                    ldsm4(ah[i], addr);
                }
#pragma unroll
                for (int jj = 0; jj < 2; ++jj) {
                    int r = bRowBase + 16 * jj;
                    uint32_t addr = base + 2 * TILE_B + (uint32_t)(r * 128)
                                  + (uint32_t)((((2 * kk + bChunkSel) ^ (r & 7)) << 4));
                    ldsm4(bh[jj], addr);
                }
            }
            // hi x hi MMAs can start while lo fragments load
#pragma unroll
            for (int i = 0; i < 2; ++i)
#pragma unroll
                for (int j = 0; j < 4; ++j)
                    mma_bf16(acc[i][j], ah[i],
                             bh[j >> 1][(j & 1) * 2], bh[j >> 1][(j & 1) * 2 + 1]);
            // lo fragments
#pragma unroll
            for (int i = 0; i < 2; ++i) {
                int r = aRowBase + 16 * i;
                uint32_t addr = base + TILE_B + (uint32_t)(r * 128)
                              + (uint32_t)((((2 * kk + aChunkSel) ^ (r & 7)) << 4));
                ldsm4(al[i], addr);
            }
#pragma unroll
            for (int jj = 0; jj < 2; ++jj) {
                int r = bRowBase + 16 * jj;
                uint32_t addr = base + 3 * TILE_B + (uint32_t)(r * 128)
                              + (uint32_t)((((2 * kk + bChunkSel) ^ (r & 7)) << 4));
                ldsm4(bl[jj], addr);
            }
#pragma unroll
            for (int i = 0; i < 2; ++i)
#pragma unroll
                for (int j = 0; j < 4; ++j)
                    mma_bf16(acc[i][j], ah[i],
                             bl[j >> 1][(j & 1) * 2], bl[j >> 1][(j & 1) * 2 + 1]);
#pragma unroll
            for (int i = 0; i < 2; ++i)
#pragma unroll
                for (int j = 0; j < 4; ++j)
                    mma_bf16(acc[i][j], al[i],
                             bh[j >> 1][(j & 1) * 2], bh[j >> 1][(j & 1) * 2 + 1]);
        }
    }

    // ---- epilogue from registers ----
    const int qrow = lane >> 2;
    const int qcol = (lane & 3) * 2;
#pragma unroll
    for (int i = 0; i < 2; ++i) {
        int r0 = m0 + wm + 16 * i + qrow;
        int r1 = r0 + 8;
#pragma unroll
        for (int j = 0; j < 4; ++j) {
            int col = n0 + wn + j * 8 + qcol;
            if (o.mode == 1) {
                float2 bv = *(const float2*)(o.bias + col);
                float g0 = gelu_exact(acc[i][j][0] + bv.x);
                float g1 = gelu_exact(acc[i][j][1] + bv.y);
                float g2 = gelu_exact(acc[i][j][2] + bv.x);
                float g3 = gelu_exact(acc[i][j][3] + bv.y);
                __nv_bfloat162 h01, h23, l01, l23;
                h01.x = __float2bfloat16(g0); h01.y = __float2bfloat16(g1);
                h23.x = __float2bfloat16(g2); h23.y = __float2bfloat16(g3);
                l01.x = __float2bfloat16(g0 - __bfloat162float(h01.x));
                l01.y = __float2bfloat16(g1 - __bfloat162float(h01.y));
                l23.x = __float2bfloat16(g2 - __bfloat162float(h23.x));
                l23.y = __float2bfloat16(g3 - __bfloat162float(h23.y));
                *(__nv_bfloat162*)(o.outH + (size_t)r0 * DIM + col) = h01;
                *(__nv_bfloat162*)(o.outH + (size_t)r1 * DIM + col) = h23;
                *(__nv_bfloat162*)(o.outL + (size_t)r0 * DIM + col) = l01;
                *(__nv_bfloat162*)(o.outL + (size_t)r1 * DIM + col) = l23;
            } else {
                if (col < o.Nreal) {
                    float2 bv = *(const float2*)(o.bias + col);
                    float2 o0, o1;
                    o0.x = acc[i][j][0] + bv.x; o0.y = acc[i][j][1] + bv.y;
                    o1.x = acc[i][j][2] + bv.x; o1.y = acc[i][j][3] + bv.y;
                    *(float2*)(o.outF + (size_t)r0 * o.Nreal + col) = o0;
                    *(float2*)(o.outF + (size_t)r1 * o.Nreal + col) = o1;
                }
            }
        }
    }
}

// ---- merged fc1: grid (18, 128); layer = bx/6, n0 = (bx%6)*128 ----
__global__ __launch_bounds__(512, 1)
void fc1_merged(const float* __restrict__ b_cls, const float* __restrict__ b_we,
                const float* __restrict__ b_ew)
{
    extern __shared__ __align__(1024) char dyn[];
    const int bx = blockIdx.x;
    const int layer = bx / 6;
    const int n0 = (bx % 6) * 128;
    const int m0 = blockIdx.y * 128;
    GemmOut o;
    o.outF = nullptr;
    o.outH = g_hh[layer];
    o.outL = g_hl[layer];
    o.bias = (layer == 0) ? b_cls : (layer == 1) ? b_we : b_ew;
    o.Nreal = DIM;
    o.mode = 1;
    gemm_core(g_xh, g_xl, g_w1h[layer], g_w1l[layer], o, m0, n0, dyn);
}

// ---- merged fc2: grid (8, 128) ----
__global__ __launch_bounds__(512, 1)
void fc2_merged(const float* __restrict__ b_cls, const float* __restrict__ b_we,
                const float* __restrict__ b_ew)
{
    extern __shared__ __align__(1024) char dyn[];
    const int bx = blockIdx.x;
    const int m0 = blockIdx.y * 128;
    GemmOut o;
    o.outH = nullptr; o.outL = nullptr; o.mode = 0;
    const __nv_bfloat16 *Ah, *Al, *Bh, *Bl;
    int n0;
    if (bx < 6) {
        Ah = g_hh[0]; Al = g_hl[0]; Bh = g_w2ch; Bl = g_w2cl;
        o.outF = g_cls_logits; o.bias = b_cls; o.Nreal = NEC; n0 = bx * 128;
    } else if (bx == 6) {
        Ah = g_hh[1]; Al = g_hl[1]; Bh = g_w2eh[0]; Bl = g_w2el[0];
        o.outF = g_we_logits; o.bias = b_we; o.Nreal = NEXP; n0 = 0;
    } else {
        Ah = g_hh[2]; Al = g_hl[2]; Bh = g_w2eh[1]; Bl = g_w2el[1];
        o.outF = g_ew_logits; o.bias = b_ew; o.Nreal = NEXP; n0 = 0;
    }
    gemm_core(Ah, Al, Bh, Bl, o, m0, n0, dyn);
}

// ---------------------------------------------------------------------------
// Row-wise epilogue — float4 rank loop, __expf softmaxes, and cls_l row
// staged through SMEM with coalesced float4 loads.
// ---------------------------------------------------------------------------
__global__ __launch_bounds__(128)
void epilogue_kernel(const float* __restrict__ we_l,
                     const float* __restrict__ ew_l,
                     const float* __restrict__ cls_l,
                     const int*   __restrict__ n_experts,
                     float* __restrict__ out)
{
    const int row  = blockIdx.x;
    const int t    = threadIdx.x;
    const int lane = t & 31;
    const int warp = t >> 5;

    __shared__ __align__(16) float s_we[128];
    __shared__ __align__(16) float s_cls[NEC];       // 744 floats
    __shared__ float s_thr;
    __shared__ float s_red[4];
    __shared__ float s_part[4][NCLS];

    const float NEG_INF = -__int_as_float(0x7f800000);

    // stage cls row: 186 float4 (row offset 744*4 B is 16B-aligned)
    {
        const float4* src = (const float4*)(cls_l + (size_t)row * NEC);
#pragma unroll
        for (int i = t; i < NEC / 4; i += 128)
            ((float4*)s_cls)[i] = src[i];
    }

    float v = (t < NEXP) ? we_l[row * NEXP + t] : NEG_INF;
    s_we[t] = v;
    __syncthreads();

    int n = n_experts[row];
    n = (n < NEXP) ? n : NEXP;

    // rank count: fgt on FMA pipe, ceq on ALU pipe; float4 LDS.
    {
        float fgt = 0.0f;
        int ceq = 0;
#pragma unroll
        for (int j = 0; j < NEXP; j += 4) {
            float4 u4 = *(const float4*)&s_we[j];
            fgt += (u4.x > v) ? 1.0f : 0.0f;  ceq += (u4.x == v);
            fgt += (u4.y > v) ? 1.0f : 0.0f;  ceq += (u4.y == v);
            fgt += (u4.z > v) ? 1.0f : 0.0f;  ceq += (u4.z == v);
            fgt += (u4.w > v) ? 1.0f : 0.0f;  ceq += (u4.w == v);
        }
        int cgt = (int)fgt;
        if (t < NEXP && cgt <= n - 1 && cgt + ceq > n - 1) s_thr = v;  // rank n-1
    }
    __syncthreads();
    float thr = s_thr;

    float ewv = NEG_INF;
    if (t < NEXP && v >= thr) ewv = ew_l[row * NEXP + t];

    float m = ewv;
#pragma unroll
    for (int o = 16; o > 0; o >>= 1) m = fmaxf(m, __shfl_xor_sync(0xffffffffu, m, o));
    if (lane == 0) s_red[warp] = m;
    __syncthreads();
    m = fmaxf(fmaxf(s_red[0], s_red[1]), fmaxf(s_red[2], s_red[3]));
    __syncthreads();

    float e = (ewv == NEG_INF) ? 0.0f : __expf(ewv - m);

    float se = e;
#pragma unroll
    for (int o = 16; o > 0; o >>= 1) se += __shfl_xor_sync(0xffffffffu, se, o);
    if (lane == 0) s_red[warp] = se;
    __syncthreads();
    se = s_red[0] + s_red[1] + s_red[2] + s_red[3];

    float part[NCLS];
#pragma unroll
    for (int c = 0; c < NCLS; c++) part[c] = 0.0f;
    if (t < NEXP) {
        float l[NCLS];
#pragma unroll
        for (int c = 0; c < NCLS; c++) l[c] = s_cls[t * NCLS + c];
        float mx = l[0];
#pragma unroll
        for (int c = 1; c < NCLS; c++) mx = fmaxf(mx, l[c]);
        float s = 0.0f;
#pragma unroll
        for (int c = 0; c < NCLS; c++) { l[c] = __expf(l[c] - mx); s += l[c]; }
        float scale = e / s;
#pragma unroll
        for (int c = 0; c < NCLS; c++) part[c] = l[c] * scale;
    }

#pragma unroll
    for (int c = 0; c < NCLS; c++) {
        float p = part[c];
#pragma unroll
        for (int o = 16; o > 0; o >>= 1) p += __shfl_xor_sync(0xffffffffu, p, o);
        part[c] = p;
    }
    if (lane == 0)
#pragma unroll
        for (int c = 0; c < NCLS; c++) s_part[warp][c] = part[c];
    __syncthreads();

    if (t < NCLS) {
        float tot = s_part[0][t] + s_part[1][t] + s_part[2][t] + s_part[3][t];
        out[row * NCLS + t] = tot / se;
    }
}

// ---------------------------------------------------------------------------
// Launch
// ---------------------------------------------------------------------------
extern "C" void kernel_launch(void* const* d_in, const int* in_sizes, int n_in,
                              void* d_out, int out_size)
{
    const float* x      = (const float*)d_in[0];
    const int*   n_exp  = (const int*)  d_in[1];
    const float* cls_w1 = (const float*)d_in[2];
    const float* cls_b1 = (const float*)d_in[3];
    const float* cls_w2 = (const float*)d_in[4];
    const float* cls_b2 = (const float*)d_in[5];
    const float* we_w1  = (const float*)d_in[6];
    const float* we_b1  = (const float*)d_in[7];
    const float* we_w2  = (const float*)d_in[8];
    const float* we_b2  = (const float*)d_in[9];
    const float* ew_w1  = (const float*)d_in[10];
    const float* ew_b1  = (const float*)d_in[11];
    const float* ew_w2  = (const float*)d_in[12];
    const float* ew_b2  = (const float*)d_in[13];
    float* out = (float*)d_out;

    float *cls_lg, *we_lg, *ew_lg;
    cudaGetSymbolAddress((void**)&cls_lg, g_cls_logits);
    cudaGetSymbolAddress((void**)&we_lg,  g_we_logits);
    cudaGetSymbolAddress((void**)&ew_lg,  g_ew_logits);

    cudaFuncSetAttribute(fc1_merged,
                         cudaFuncAttributeMaxDynamicSharedMemorySize, SMEM_TOTAL);
    cudaFuncSetAttribute(fc2_merged,
                         cudaFuncAttributeMaxDynamicSharedMemorySize, SMEM_TOTAL);

    // 1) merged prep (flat grid, zero wasted blocks)
    dim3 tb(32, 8);
    prep_all_k<<<PREP_BLOCKS, tb>>>(x, cls_w1, we_w1, ew_w1,
                                    cls_w2, we_w2, ew_w2);

    // 2) fc1 merged (+gelu, split-bf16 output)
    fc1_merged<<<dim3(18, BATCH / 128), 512, SMEM_TOTAL>>>(cls_b1, we_b1, ew_b1);

    // 3) fc2 merged -> fp32 logits
    fc2_merged<<<dim3(8, BATCH / 128), 512, SMEM_TOTAL>>>(cls_b2, we_b2, ew_b2);

    // 4) row-wise softmax/topk epilogue
    epilogue_kernel<<<BATCH, 128>>>(we_lg, ew_lg, cls_lg, n_exp, out);
}